// round 1
// baseline (speedup 1.0000x reference)
#include <cuda_runtime.h>

#define TN 64          // nodes per tile
#define CC 128         // channels
#define KD 32          // super nodes

#define XS_PITCH 68    // floats per channel row of x tile (k-major), mod-4 aligned
#define HS_PITCH 132   // floats per node row of h tile (conflict-free for stage2)

// shared-memory layout (bytes). W1 region is overlaid by hs/W2s/ls/ss after stage 1.
#define XS_OFF   0
#define XS_BYTES (CC * XS_PITCH * 4)            // 34816
#define UN_OFF   XS_BYTES
#define HS_OFF   UN_OFF                          // 64*132*4 = 33792
#define HS_BYTES (TN * HS_PITCH * 4)
#define W2_OFF   (HS_OFF + HS_BYTES)             // 68608, 16384 B
#define W2_BYTES (CC * KD * 4)
#define LS_OFF   (W2_OFF + W2_BYTES)             // 84992, 8192 B
#define LS_BYTES (TN * KD * 4)
#define SS_OFF   (LS_OFF + LS_BYTES)             // 93184, 8192 B
#define SS_BYTES (TN * KD * 4)
#define IB_OFF   (SS_OFF + SS_BYTES)             // 101376
#define SMEM_BYTES (IB_OFF + TN * 4)             // 101632

__global__ void hp_zero_kernel(float4* __restrict__ o, int n4) {
    int i = blockIdx.x * blockDim.x + threadIdx.x;
    float4 z = make_float4(0.f, 0.f, 0.f, 0.f);
    for (; i < n4; i += gridDim.x * blockDim.x) o[i] = z;
}

__global__ __launch_bounds__(256, 2)
void hp_main_kernel(const float* __restrict__ x, const int* __restrict__ batch,
                    const float* __restrict__ W1, const float* __restrict__ b1,
                    const float* __restrict__ W2, const float* __restrict__ b2,
                    float* __restrict__ out, float* __restrict__ s_out, int N)
{
    extern __shared__ __align__(16) char smem[];
    float*  xs   = (float*)(smem + XS_OFF);
    float4* xs4  = (float4*)xs;
    float4* W1s4 = (float4*)(smem + UN_OFF);
    float*  hs   = (float*)(smem + HS_OFF);
    float*  W2s  = (float*)(smem + W2_OFF);
    float*  ls   = (float*)(smem + LS_OFF);
    float*  ss   = (float*)(smem + SS_OFF);
    int*    ib   = (int*)(smem + IB_OFF);

    const int tid = threadIdx.x;
    const int tx  = tid & 31;
    const int ty  = tid >> 5;          // 0..7
    const int n0  = blockIdx.x * TN;
    const int nvalid = min(TN, N - n0);

    // ---- load tile: batch ids, x (k-major), W1 (full, float4) ----
    if (tid < TN) ib[tid] = (n0 + tid < N) ? batch[n0 + tid] : -1;

    for (int idx = tid; idx < TN * CC; idx += 256) {
        int n = idx >> 7;
        int k = idx & 127;
        xs[k * XS_PITCH + n] = (n < nvalid) ? x[(size_t)(n0 + n) * CC + k] : 0.f;
    }
    {
        const float4* g = (const float4*)W1;
        #pragma unroll 4
        for (int i = tid; i < CC * CC / 4; i += 256) W1s4[i] = g[i];
    }
    __syncthreads();

    // ---- stage 1: H = relu(X @ W1 + b1). thread -> cols j = tx*4+c, rows n = ty*8+r ----
    float acc[8][4];
    {
        float4 bb = ((const float4*)b1)[tx];
        #pragma unroll
        for (int r = 0; r < 8; ++r) {
            acc[r][0] = bb.x; acc[r][1] = bb.y; acc[r][2] = bb.z; acc[r][3] = bb.w;
        }
        #pragma unroll 4
        for (int k = 0; k < CC; ++k) {
            float4 wv = W1s4[k * (CC / 4) + tx];
            float4 xa = xs4[k * (XS_PITCH / 4) + ty * 2];
            float4 xb = xs4[k * (XS_PITCH / 4) + ty * 2 + 1];
            float xr[8] = {xa.x, xa.y, xa.z, xa.w, xb.x, xb.y, xb.z, xb.w};
            float wc[4] = {wv.x, wv.y, wv.z, wv.w};
            #pragma unroll
            for (int r = 0; r < 8; ++r)
                #pragma unroll
                for (int c = 0; c < 4; ++c)
                    acc[r][c] = fmaf(xr[r], wc[c], acc[r][c]);
        }
    }
    __syncthreads();   // everyone done reading W1s before hs/W2s overlay it

    #pragma unroll
    for (int r = 0; r < 8; ++r) {
        int n = ty * 8 + r;
        float4 v;
        v.x = fmaxf(acc[r][0], 0.f);
        v.y = fmaxf(acc[r][1], 0.f);
        v.z = fmaxf(acc[r][2], 0.f);
        v.w = fmaxf(acc[r][3], 0.f);
        *(float4*)&hs[n * HS_PITCH + tx * 4] = v;
    }
    #pragma unroll 4
    for (int i = tid; i < CC * KD; i += 256) W2s[i] = W2[i];
    __syncthreads();

    // ---- stage 2: logits = H @ W2 + b2. thread -> node pair np, kk group kg (4 kk) ----
    {
        const int np = tid >> 3;   // 0..31 -> nodes 2np, 2np+1
        const int kg = tid & 7;    // kk = kg*4 + i
        float4 b2v = ((const float4*)b2)[kg];
        float a0[4] = {b2v.x, b2v.y, b2v.z, b2v.w};
        float a1[4] = {b2v.x, b2v.y, b2v.z, b2v.w};
        const float* h0p = &hs[(2 * np) * HS_PITCH];
        const float* h1p = h0p + HS_PITCH;
        #pragma unroll 4
        for (int j = 0; j < CC; ++j) {
            float h0 = h0p[j];
            float h1 = h1p[j];
            float4 w = *(const float4*)&W2s[j * KD + kg * 4];
            float wc[4] = {w.x, w.y, w.z, w.w};
            #pragma unroll
            for (int i = 0; i < 4; ++i) {
                a0[i] = fmaf(h0, wc[i], a0[i]);
                a1[i] = fmaf(h1, wc[i], a1[i]);
            }
        }
        *(float4*)&ls[(2 * np) * KD + kg * 4]     = make_float4(a0[0], a0[1], a0[2], a0[3]);
        *(float4*)&ls[(2 * np + 1) * KD + kg * 4] = make_float4(a1[0], a1[1], a1[2], a1[3]);
    }
    __syncthreads();

    // ---- stage 3: softmax per node (warp per node, lane = kk) ----
    {
        const int lane = tx;
        for (int n = ty; n < TN; n += 8) {
            float v = ls[n * KD + lane];
            float m = v;
            #pragma unroll
            for (int o = 16; o > 0; o >>= 1) m = fmaxf(m, __shfl_xor_sync(0xffffffffu, m, o));
            float e = __expf(v - m);
            float sum = e;
            #pragma unroll
            for (int o = 16; o > 0; o >>= 1) sum += __shfl_xor_sync(0xffffffffu, sum, o);
            float sv = e / sum;
            ss[n * KD + lane] = sv;
            if (n0 + n < N) s_out[(size_t)(n0 + n) * KD + lane] = sv;
        }
    }
    __syncthreads();

    // ---- stage 4: per-segment P[k][c] = sum_n s[n][k]*x[n][c], atomic add into out ----
    {
        int bmin = ib[0];
        int bmax = ib[nvalid - 1];
        for (int b = bmin; b <= bmax; ++b) {
            float p[4][4];   // [kq][cc]
            #pragma unroll
            for (int kq = 0; kq < 4; ++kq)
                #pragma unroll
                for (int cc = 0; cc < 4; ++cc) p[kq][cc] = 0.f;

            for (int n = 0; n < TN; ++n) {
                if (ib[n] != b) continue;   // uniform across block
                float sv[4], xv[4];
                #pragma unroll
                for (int kq = 0; kq < 4; ++kq) sv[kq] = ss[n * KD + ty * 4 + kq];
                #pragma unroll
                for (int cc = 0; cc < 4; ++cc) xv[cc] = xs[(cc * 32 + tx) * XS_PITCH + n];
                #pragma unroll
                for (int kq = 0; kq < 4; ++kq)
                    #pragma unroll
                    for (int cc = 0; cc < 4; ++cc)
                        p[kq][cc] = fmaf(sv[kq], xv[cc], p[kq][cc]);
            }
            float* ob = out + (size_t)b * (KD * CC);
            #pragma unroll
            for (int kq = 0; kq < 4; ++kq)
                #pragma unroll
                for (int cc = 0; cc < 4; ++cc)
                    atomicAdd(&ob[(ty * 4 + kq) * CC + cc * 32 + tx], p[kq][cc]);
        }
    }
}

extern "C" void kernel_launch(void* const* d_in, const int* in_sizes, int n_in,
                              void* d_out, int out_size)
{
    const float* x     = (const float*)d_in[0];
    const int*   batch = (const int*)d_in[1];
    const float* W1    = (const float*)d_in[2];
    const float* b1    = (const float*)d_in[3];
    const float* W2    = (const float*)d_in[4];
    const float* b2    = (const float*)d_in[5];

    const int N = in_sizes[1];                       // batch vector length
    float* out = (float*)d_out;
    // output tuple (out[B,K,C], s[N,K]) flattened in order
    size_t out_elems = (size_t)out_size - (size_t)N * KD;   // B*K*C
    float* s_out = out + out_elems;

    // zero the pooled-output region (poisoned by harness)
    {
        int n4 = (int)(out_elems / 4);
        int blocks = (n4 + 255) / 256;
        if (blocks > 512) blocks = 512;
        hp_zero_kernel<<<blocks, 256>>>((float4*)out, n4);
    }

    cudaFuncSetAttribute(hp_main_kernel,
                         cudaFuncAttributeMaxDynamicSharedMemorySize, SMEM_BYTES);
    int nb = (N + TN - 1) / TN;
    hp_main_kernel<<<nb, 256, SMEM_BYTES>>>(x, batch, W1, b1, W2, b2, out, s_out, N);
}

// round 2
// speedup vs baseline: 1.2297x; 1.2297x over previous
#include <cuda_runtime.h>

#define TN 64          // nodes per tile
#define CC 128         // channels
#define KD 32          // super nodes

#define XS_PITCH 68    // k-major x tile pitch (floats), float4-aligned
#define HS_PITCH 132   // node-major h tile pitch
#define XN_PITCH 129   // node-major x copy pitch (odd -> conflict-free transposed use)

// shared-memory layout (bytes). W1 region overlaid by hs, then hs overlaid by xsn.
#define XS_OFF   0
#define XS_BYTES (CC * XS_PITCH * 4)             // 34816
#define UN_OFF   XS_BYTES
#define HS_OFF   UN_OFF                          // hs: 64*132*4 = 33792 ; xsn: 64*129*4 = 33024
#define HS_BYTES (TN * HS_PITCH * 4)
#define W2_OFF   (HS_OFF + HS_BYTES)             // 16384 B
#define W2_BYTES (CC * KD * 4)
#define LS_OFF   (W2_OFF + W2_BYTES)             // 8192 B
#define LS_BYTES (TN * KD * 4)
#define SS_OFF   (LS_OFF + LS_BYTES)             // 8192 B
#define SS_BYTES (TN * KD * 4)
#define IB_OFF   (SS_OFF + SS_BYTES)
#define SMEM_BYTES (IB_OFF + TN * 4)             // 101632

typedef unsigned long long ull;

__device__ __forceinline__ ull pk2(float lo, float hi) {
    ull r; asm("mov.b64 %0, {%1,%2};" : "=l"(r) : "f"(lo), "f"(hi)); return r;
}
__device__ __forceinline__ float2 upk2(ull v) {
    float2 f; asm("mov.b64 {%0,%1}, %2;" : "=f"(f.x), "=f"(f.y) : "l"(v)); return f;
}
__device__ __forceinline__ ull ffma2_(ull a, ull b, ull c) {
    ull d; asm("fma.rn.f32x2 %0, %1, %2, %3;" : "=l"(d) : "l"(a), "l"(b), "l"(c)); return d;
}

__global__ void hp_zero_kernel(float4* __restrict__ o, int n4) {
    int i = blockIdx.x * blockDim.x + threadIdx.x;
    float4 z = make_float4(0.f, 0.f, 0.f, 0.f);
    for (; i < n4; i += gridDim.x * blockDim.x) o[i] = z;
}

__global__ __launch_bounds__(256, 2)
void hp_main_kernel(const float* __restrict__ x, const int* __restrict__ batch,
                    const float* __restrict__ W1, const float* __restrict__ b1,
                    const float* __restrict__ W2, const float* __restrict__ b2,
                    float* __restrict__ out, float* __restrict__ s_out, int N)
{
    extern __shared__ __align__(16) char smem[];
    float*  xs   = (float*)(smem + XS_OFF);
    float4* xs4  = (float4*)xs;
    float4* W1s4 = (float4*)(smem + UN_OFF);
    float*  hs   = (float*)(smem + HS_OFF);
    float*  xsn  = (float*)(smem + HS_OFF);      // overlays hs after stage 2
    float*  W2s  = (float*)(smem + W2_OFF);
    float*  ls   = (float*)(smem + LS_OFF);
    float*  ss   = (float*)(smem + SS_OFF);
    int*    ib   = (int*)(smem + IB_OFF);

    const int tid = threadIdx.x;
    const int tx  = tid & 31;
    const int ty  = tid >> 5;          // 0..7
    const int n0  = blockIdx.x * TN;
    const int nvalid = min(TN, N - n0);

    // ---- load tile: batch ids, x (k-major), W1 (full, float4) ----
    if (tid < TN) ib[tid] = (n0 + tid < N) ? batch[n0 + tid] : -1;

    for (int idx = tid; idx < TN * CC; idx += 256) {
        int n = idx >> 7;
        int k = idx & 127;
        xs[k * XS_PITCH + n] = (n < nvalid) ? x[(size_t)(n0 + n) * CC + k] : 0.f;
    }
    {
        const float4* g = (const float4*)W1;
        #pragma unroll 4
        for (int i = tid; i < CC * CC / 4; i += 256) W1s4[i] = g[i];
    }
    __syncthreads();

    // ---- stage 1: H = relu(X @ W1 + b1), f32x2 packed over node pairs ----
    // thread -> cols j = tx*4+c (c=0..3), nodes n = ty*8 + 2*rp + {0,1} (rp=0..3)
    ull acc2[4][4];
    {
        float4 bb = ((const float4*)b1)[tx];
        float bc[4] = {bb.x, bb.y, bb.z, bb.w};
        #pragma unroll
        for (int rp = 0; rp < 4; ++rp)
            #pragma unroll
            for (int c = 0; c < 4; ++c) acc2[rp][c] = pk2(bc[c], bc[c]);

        #pragma unroll 2
        for (int k = 0; k < CC; ++k) {
            float4 wv = W1s4[k * (CC / 4) + tx];
            float4 xa = xs4[k * (XS_PITCH / 4) + ty * 2];
            float4 xb = xs4[k * (XS_PITCH / 4) + ty * 2 + 1];
            ull xp[4] = {pk2(xa.x, xa.y), pk2(xa.z, xa.w),
                         pk2(xb.x, xb.y), pk2(xb.z, xb.w)};
            ull wp[4] = {pk2(wv.x, wv.x), pk2(wv.y, wv.y),
                         pk2(wv.z, wv.z), pk2(wv.w, wv.w)};
            #pragma unroll
            for (int rp = 0; rp < 4; ++rp)
                #pragma unroll
                for (int c = 0; c < 4; ++c)
                    acc2[rp][c] = ffma2_(xp[rp], wp[c], acc2[rp][c]);
        }
    }
    __syncthreads();   // done reading W1s before hs overlays it

    #pragma unroll
    for (int rp = 0; rp < 4; ++rp) {
        float2 f0 = upk2(acc2[rp][0]);
        float2 f1 = upk2(acc2[rp][1]);
        float2 f2 = upk2(acc2[rp][2]);
        float2 f3 = upk2(acc2[rp][3]);
        int na = ty * 8 + 2 * rp;
        float4 va = make_float4(fmaxf(f0.x, 0.f), fmaxf(f1.x, 0.f),
                                fmaxf(f2.x, 0.f), fmaxf(f3.x, 0.f));
        float4 vb = make_float4(fmaxf(f0.y, 0.f), fmaxf(f1.y, 0.f),
                                fmaxf(f2.y, 0.f), fmaxf(f3.y, 0.f));
        *(float4*)&hs[na * HS_PITCH + tx * 4]       = va;
        *(float4*)&hs[(na + 1) * HS_PITCH + tx * 4] = vb;
    }
    #pragma unroll 4
    for (int i = tid; i < CC * KD; i += 256) W2s[i] = W2[i];
    __syncthreads();

    // ---- stage 2: logits = H @ W2 + b2, f32x2 packed over kk pairs ----
    {
        const int np = tid >> 3;   // nodes 2np, 2np+1
        const int kg = tid & 7;    // kk = kg*4 + {0..3}
        float4 b2v = ((const float4*)b2)[kg];
        ull a0[2] = {pk2(b2v.x, b2v.y), pk2(b2v.z, b2v.w)};
        ull a1[2] = {a0[0], a0[1]};
        const float* h0p = &hs[(2 * np) * HS_PITCH];
        const float* h1p = h0p + HS_PITCH;
        #pragma unroll 4
        for (int j = 0; j < CC; ++j) {
            float h0 = h0p[j];
            float h1 = h1p[j];
            ull h0p2 = pk2(h0, h0);
            ull h1p2 = pk2(h1, h1);
            float4 w = *(const float4*)&W2s[j * KD + kg * 4];
            ull wp0 = pk2(w.x, w.y);
            ull wp1 = pk2(w.z, w.w);
            a0[0] = ffma2_(h0p2, wp0, a0[0]);
            a0[1] = ffma2_(h0p2, wp1, a0[1]);
            a1[0] = ffma2_(h1p2, wp0, a1[0]);
            a1[1] = ffma2_(h1p2, wp1, a1[1]);
        }
        float2 r00 = upk2(a0[0]), r01 = upk2(a0[1]);
        float2 r10 = upk2(a1[0]), r11 = upk2(a1[1]);
        *(float4*)&ls[(2 * np) * KD + kg * 4]     = make_float4(r00.x, r00.y, r01.x, r01.y);
        *(float4*)&ls[(2 * np + 1) * KD + kg * 4] = make_float4(r10.x, r10.y, r11.x, r11.y);
    }
    __syncthreads();

    // ---- stage 3: softmax per node (warp per node, lane = kk) ----
    {
        const int lane = tx;
        for (int n = ty; n < TN; n += 8) {
            float v = ls[n * KD + lane];
            float m = v;
            #pragma unroll
            for (int o = 16; o > 0; o >>= 1) m = fmaxf(m, __shfl_xor_sync(0xffffffffu, m, o));
            float e = __expf(v - m);
            float sum = e;
            #pragma unroll
            for (int o = 16; o > 0; o >>= 1) sum += __shfl_xor_sync(0xffffffffu, sum, o);
            float sv = e / sum;
            ss[n * KD + lane] = sv;
            if (n0 + n < N) s_out[(size_t)(n0 + n) * KD + lane] = sv;
        }
    }
    __syncthreads();

    // ---- transpose x into node-major copy (conflict-free both directions) ----
    for (int idx = tid; idx < TN * CC; idx += 256) {
        int n = idx & 63;
        int k = idx >> 6;
        xsn[n * XN_PITCH + k] = xs[k * XS_PITCH + n];
    }
    __syncthreads();

    // ---- stage 4: per-segment P[k][c] = sum_n s[n][k]*x[n][c], f32x2 over kq pairs ----
    {
        int bmin = ib[0];
        int bmax = ib[nvalid - 1];
        for (int b = bmin; b <= bmax; ++b) {
            ull p2[2][4];
            #pragma unroll
            for (int kp = 0; kp < 2; ++kp)
                #pragma unroll
                for (int cc = 0; cc < 4; ++cc) p2[kp][cc] = 0ull;

            for (int n = 0; n < TN; ++n) {
                if (ib[n] != b) continue;   // uniform across block
                ull sv01 = *(const ull*)&ss[n * KD + ty * 4];
                ull sv23 = *(const ull*)&ss[n * KD + ty * 4 + 2];
                #pragma unroll
                for (int cc = 0; cc < 4; ++cc) {
                    float xv = xsn[n * XN_PITCH + cc * 32 + tx];
                    ull xp = pk2(xv, xv);
                    p2[0][cc] = ffma2_(sv01, xp, p2[0][cc]);
                    p2[1][cc] = ffma2_(sv23, xp, p2[1][cc]);
                }
            }
            float* ob = out + (size_t)b * (KD * CC);
            #pragma unroll
            for (int kp = 0; kp < 2; ++kp)
                #pragma unroll
                for (int cc = 0; cc < 4; ++cc) {
                    float2 f = upk2(p2[kp][cc]);
                    atomicAdd(&ob[(ty * 4 + kp * 2)     * CC + cc * 32 + tx], f.x);
                    atomicAdd(&ob[(ty * 4 + kp * 2 + 1) * CC + cc * 32 + tx], f.y);
                }
        }
    }
}

extern "C" void kernel_launch(void* const* d_in, const int* in_sizes, int n_in,
                              void* d_out, int out_size)
{
    const float* x     = (const float*)d_in[0];
    const int*   batch = (const int*)d_in[1];
    const float* W1    = (const float*)d_in[2];
    const float* b1    = (const float*)d_in[3];
    const float* W2    = (const float*)d_in[4];
    const float* b2    = (const float*)d_in[5];

    const int N = in_sizes[1];
    float* out = (float*)d_out;
    size_t out_elems = (size_t)out_size - (size_t)N * KD;   // B*K*C
    float* s_out = out + out_elems;

    {
        int n4 = (int)(out_elems / 4);
        int blocks = (n4 + 255) / 256;
        if (blocks > 512) blocks = 512;
        hp_zero_kernel<<<blocks, 256>>>((float4*)out, n4);
    }

    cudaFuncSetAttribute(hp_main_kernel,
                         cudaFuncAttributeMaxDynamicSharedMemorySize, SMEM_BYTES);
    int nb = (N + TN - 1) / TN;
    hp_main_kernel<<<nb, 256, SMEM_BYTES>>>(x, batch, W1, b1, W2, b2, out, s_out, N);
}